// round 14
// baseline (speedup 1.0000x reference)
#include <cuda_runtime.h>
#include <cstdint>
#include <cstddef>

// ---------------------------------------------------------------------------
// SimultaneousRetrievalModel on GB300 (sm_103a)
// R14: two-phase. Kmain = down-proj (8 rows/warp, 2x weight amortization)
// + sims/softmax/retrieved, writes rv_ext[B][116] (c-scaled, conf appended)
// to __device__ global. K3 = tiled GEMM out = rv_ext @ Fu^T + bc (Fu read
// once per 128 rows). Fu = Wc@[Wu_cat|bu] precomputed.
// ---------------------------------------------------------------------------

#define WARPS 18
#define NTHR  (WARPS * 32)
#define NB    152
#define MAXB  131072

typedef unsigned long long u64;

__device__ __forceinline__ u64 pack2(float lo, float hi) {
    u64 r; asm("mov.b64 %0, {%1, %2};" : "=l"(r) : "f"(lo), "f"(hi)); return r;
}
__device__ __forceinline__ void unpack2(u64 v, float& lo, float& hi) {
    asm("mov.b64 {%0, %1}, %2;" : "=f"(lo), "=f"(hi) : "l"(v));
}
__device__ __forceinline__ u64 fma2(u64 a, u64 b, u64 c) {
    u64 d; asm("fma.rn.f32x2 %0, %1, %2, %3;" : "=l"(d) : "l"(a), "l"(b), "l"(c)); return d;
}

__device__ float g_Fu[64 * 115];          // fused Wc@[Wu_cat | bu0 bu1 bu2]
__device__ float g_rv[(size_t)MAXB * 116]; // rv_ext: c*retrieved (112) + c0 c1 c2 + pad

__global__ void precompute_fu(const float* __restrict__ Wc,
                              const float* __restrict__ Wu0,
                              const float* __restrict__ Wu1,
                              const float* __restrict__ Wu2,
                              const float* __restrict__ bu0,
                              const float* __restrict__ bu1,
                              const float* __restrict__ bu2) {
    __shared__ float wc_row[64];
    int o = blockIdx.x;       // 64 blocks
    int j = threadIdx.x;      // 128 threads
    if (j < 64) wc_row[j] = Wc[o * 64 + j];
    __syncthreads();
    if (j < 115) {
        float s = 0.f;
        if (j < 64) {
            for (int h = 0; h < 64; h++) s += wc_row[h] * Wu0[h * 64 + j];
        } else if (j < 96) {
            int jj = j - 64;
            for (int h = 0; h < 64; h++) s += wc_row[h] * Wu1[h * 32 + jj];
        } else if (j < 112) {
            int jj = j - 96;
            for (int h = 0; h < 64; h++) s += wc_row[h] * Wu2[h * 16 + jj];
        } else {
            const float* bu = (j == 112) ? bu0 : (j == 113) ? bu1 : bu2;
            for (int h = 0; h < 64; h++) s += wc_row[h] * bu[h];
        }
        g_Fu[o * 115 + j] = s;
    }
}

// =========================== Kmain ===========================
// block smem: Wp[112][65] + bp[112]; per-warp: alias{qt[64][10] | mem0/1/2} 800,
// qp[8][112] 896, w_s 32 -> stride 1728
#define OFF_WP   0
#define OFF_BP   7280
#define OFF_WARP 7392
#define S_ALIAS  0         // qt (step A) / mem staging (steps B-E)
#define S_QP     800
#define S_W      1696
#define W_STRIDE 1728
#define SMEM_FLOATS (OFF_WARP + WARPS * W_STRIDE)
#define SMEM_BYTES  (SMEM_FLOATS * 4)

__global__ void __launch_bounds__(NTHR, 1) retrieval_main(
    const float* __restrict__ q_g,
    const float* __restrict__ m0_g,
    const float* __restrict__ m1_g,
    const float* __restrict__ m2_g,
    const float* __restrict__ Wp0, const float* __restrict__ bp0,
    const float* __restrict__ Wp1, const float* __restrict__ bp1,
    const float* __restrict__ Wp2, const float* __restrict__ bp2,
    int nrows)
{
    extern __shared__ float sm[];
    const int tid  = threadIdx.x;
    const int wid  = tid >> 5;
    const int lane = tid & 31;

    // ---- stage Wp/bp (pre-scaled by 1/sqrt(dim)) ----
    {
        const float s0 = 0.125f;
        const float s1 = 0.17677669529663687f;
        const float s2 = 0.25f;
        for (int idx = tid; idx < 112 * 64; idx += NTHR) {
            int j = idx >> 6, h = idx & 63;
            float v;
            if (j < 64)      v = Wp0[j * 64 + h] * s0;
            else if (j < 96) v = Wp1[(j - 64) * 64 + h] * s1;
            else             v = Wp2[(j - 96) * 64 + h] * s2;
            sm[OFF_WP + j * 65 + h] = v;
        }
        for (int j = tid; j < 112; j += NTHR) {
            float v;
            if (j < 64)      v = bp0[j] * s0;
            else if (j < 96) v = bp1[j - 64] * s1;
            else             v = bp2[j - 96] * s2;
            sm[OFF_BP + j] = v;
        }
    }
    __syncthreads();

    float* wbase = sm + OFF_WARP + wid * W_STRIDE;
    float* qt    = wbase + S_ALIAS;        // [64][10], step A only
    float* mem0  = wbase + S_ALIAS;        // [4][65]  = 264  (aliases qt)
    float* mem1  = wbase + S_ALIAS + 264;  // [8][33]  = 264
    float* mem2  = wbase + S_ALIAS + 528;  // [16][17] = 272
    float* qp_s  = wbase + S_QP;           // [8][112]
    float* w_s   = wbase + S_W;            // [28]

    const float* Wp_s = sm + OFF_WP;
    const float* bp_s = sm + OFF_BP;

    const int gw = blockIdx.x * WARPS + wid;
    const int ngroups = (nrows + 7) >> 3;
    const int gstride = gridDim.x * WARPS;

    for (int g = gw; g < ngroups; g += gstride) {
        const int r0 = g * 8;

        // ---- load q for 8 rows, transposed: qt[h*10 + r] ----
        #pragma unroll
        for (int r = 0; r < 8; r++) {
            int row = min(r0 + r, nrows - 1);
            qt[lane * 10 + r]        = q_g[(size_t)row * 64 + lane];
            qt[(lane + 32) * 10 + r] = q_g[(size_t)row * 64 + lane + 32];
        }
        __syncwarp();

        // ---- step A: down-proj for 8 rows (4 pairs) ----
        {
            int j3 = (lane < 16) ? (lane + 96) : (lane + 64);
            int js[4] = { lane, lane + 32, lane + 64, j3 };
            u64 ac[4][4];   // [j-slot][row-pair]
            #pragma unroll
            for (int k = 0; k < 4; k++) {
                float b = bp_s[js[k]];
                u64 bb = pack2(b, b);
                ac[k][0] = bb; ac[k][1] = bb; ac[k][2] = bb; ac[k][3] = bb;
            }
            #pragma unroll 2
            for (int h = 0; h < 64; h++) {
                u64 qa = *(const u64*)&qt[h * 10];
                u64 qb = *(const u64*)&qt[h * 10 + 2];
                u64 qc = *(const u64*)&qt[h * 10 + 4];
                u64 qd = *(const u64*)&qt[h * 10 + 6];
                #pragma unroll
                for (int k = 0; k < 4; k++) {
                    float w = Wp_s[js[k] * 65 + h];
                    u64 ww = pack2(w, w);
                    ac[k][0] = fma2(ww, qa, ac[k][0]);
                    ac[k][1] = fma2(ww, qb, ac[k][1]);
                    ac[k][2] = fma2(ww, qc, ac[k][2]);
                    ac[k][3] = fma2(ww, qd, ac[k][3]);
                }
            }
            #pragma unroll
            for (int k = 0; k < 4; k++) {
                if (k == 3 && lane >= 16) break;
                #pragma unroll
                for (int p = 0; p < 4; p++) {
                    float v0, v1;
                    unpack2(ac[k][p], v0, v1);
                    qp_s[(2 * p) * 112 + js[k]]     = v0;
                    qp_s[(2 * p + 1) * 112 + js[k]] = v1;
                }
            }
        }
        __syncwarp();   // qt dead; staging may overwrite

        // ---- steps B-E per row ----
        for (int r = 0; r < 8; r++) {
            int row = min(r0 + r, nrows - 1);

            const float4* f0 = (const float4*)(m0_g + (size_t)row * 256);
            const float4* f1 = (const float4*)(m1_g + (size_t)row * 256);
            const float4* f2 = (const float4*)(m2_g + (size_t)row * 256);
            float ch0[8], ch1[8], ch2[8];
            *(float4*)&ch0[0] = f0[2 * lane];
            *(float4*)&ch0[4] = f0[2 * lane + 1];
            *(float4*)&ch1[0] = f1[2 * lane];
            *(float4*)&ch1[4] = f1[2 * lane + 1];
            *(float4*)&ch2[0] = f2[2 * lane];
            *(float4*)&ch2[4] = f2[2 * lane + 1];

            const float* qpr = qp_s + r * 112;
            float conf0, conf1, conf2;

            // tier0: lane = (s<<3)|hg
            {
                int hg = lane & 7;
                float qph[8];
                *(float4*)&qph[0] = *(const float4*)&qpr[hg * 8];
                *(float4*)&qph[4] = *(const float4*)&qpr[hg * 8 + 4];
                float acc = 0.f;
                #pragma unroll
                for (int k = 0; k < 8; k++) acc += ch0[k] * qph[k];
                acc += __shfl_xor_sync(0xffffffffu, acc, 1);
                acc += __shfl_xor_sync(0xffffffffu, acc, 2);
                acc += __shfl_xor_sync(0xffffffffu, acc, 4);
                float mx = acc;
                mx = fmaxf(mx, __shfl_xor_sync(0xffffffffu, mx, 8));
                mx = fmaxf(mx, __shfl_xor_sync(0xffffffffu, mx, 16));
                float e = __expf(acc - mx);
                float se = e;
                se += __shfl_xor_sync(0xffffffffu, se, 8);
                se += __shfl_xor_sync(0xffffffffu, se, 16);
                float inv = 1.f / se;
                if ((lane & 7) == 0) w_s[lane >> 3] = e * inv;
                conf0 = inv;
            }
            // tier1: lane = (s<<2)|hg
            {
                int hg = lane & 3;
                float qph[8];
                *(float4*)&qph[0] = *(const float4*)&qpr[64 + hg * 8];
                *(float4*)&qph[4] = *(const float4*)&qpr[64 + hg * 8 + 4];
                float acc = 0.f;
                #pragma unroll
                for (int k = 0; k < 8; k++) acc += ch1[k] * qph[k];
                acc += __shfl_xor_sync(0xffffffffu, acc, 1);
                acc += __shfl_xor_sync(0xffffffffu, acc, 2);
                float mx = acc;
                mx = fmaxf(mx, __shfl_xor_sync(0xffffffffu, mx, 4));
                mx = fmaxf(mx, __shfl_xor_sync(0xffffffffu, mx, 8));
                mx = fmaxf(mx, __shfl_xor_sync(0xffffffffu, mx, 16));
                float e = __expf(acc - mx);
                float se = e;
                se += __shfl_xor_sync(0xffffffffu, se, 4);
                se += __shfl_xor_sync(0xffffffffu, se, 8);
                se += __shfl_xor_sync(0xffffffffu, se, 16);
                float inv = 1.f / se;
                if ((lane & 3) == 0) w_s[4 + (lane >> 2)] = e * inv;
                conf1 = inv;
            }
            // tier2: lane = (s<<1)|hg
            {
                int hg = lane & 1;
                float qph[8];
                *(float4*)&qph[0] = *(const float4*)&qpr[96 + hg * 8];
                *(float4*)&qph[4] = *(const float4*)&qpr[96 + hg * 8 + 4];
                float acc = 0.f;
                #pragma unroll
                for (int k = 0; k < 8; k++) acc += ch2[k] * qph[k];
                acc += __shfl_xor_sync(0xffffffffu, acc, 1);
                float mx = acc;
                mx = fmaxf(mx, __shfl_xor_sync(0xffffffffu, mx, 2));
                mx = fmaxf(mx, __shfl_xor_sync(0xffffffffu, mx, 4));
                mx = fmaxf(mx, __shfl_xor_sync(0xffffffffu, mx, 8));
                mx = fmaxf(mx, __shfl_xor_sync(0xffffffffu, mx, 16));
                float e = __expf(acc - mx);
                float se = e;
                se += __shfl_xor_sync(0xffffffffu, se, 2);
                se += __shfl_xor_sync(0xffffffffu, se, 4);
                se += __shfl_xor_sync(0xffffffffu, se, 8);
                se += __shfl_xor_sync(0xffffffffu, se, 16);
                float inv = 1.f / se;
                if ((lane & 1) == 0) w_s[12 + (lane >> 1)] = e * inv;
                conf2 = inv;
            }

            float mm = fmaxf(conf0, fmaxf(conf1, conf2));
            float e0 = __expf(conf0 - mm), e1 = __expf(conf1 - mm), e2 = __expf(conf2 - mm);
            float cinv = 1.f / (e0 + e1 + e2);
            float c0 = e0 * cinv, c1 = e1 * cinv, c2 = e2 * cinv;

            // stage chunks into padded smem for retrieved
            {
                float* d0 = &mem0[(lane >> 3) * 65 + (lane & 7) * 8];
                float* d1 = &mem1[(lane >> 2) * 33 + (lane & 3) * 8];
                float* d2 = &mem2[(lane >> 1) * 17 + (lane & 1) * 8];
                #pragma unroll
                for (int k = 0; k < 8; k++) d0[k] = ch0[k];
                #pragma unroll
                for (int k = 0; k < 8; k++) d1[k] = ch1[k];
                #pragma unroll
                for (int k = 0; k < 8; k++) d2[k] = ch2[k];
            }
            __syncwarp();

            // retrieved (c-scaled) -> global rv_ext
            bool live = (r0 + r) < nrows;
            float* rvb = g_rv + (size_t)(r0 + r) * 116;
            {
                float w0 = w_s[0], w1 = w_s[1], w2 = w_s[2], w3 = w_s[3];
                #pragma unroll
                for (int jj = 0; jj < 2; jj++) {
                    int j = lane + jj * 32;
                    float a = w0 * mem0[j] + w1 * mem0[65 + j]
                            + w2 * mem0[130 + j] + w3 * mem0[195 + j];
                    if (live) rvb[j] = c0 * a;
                }
            }
            {
                float a = 0.f;
                #pragma unroll
                for (int s2 = 0; s2 < 8; s2++) a += w_s[4 + s2] * mem1[s2 * 33 + lane];
                if (live) rvb[64 + lane] = c1 * a;
            }
            if (lane < 16) {
                float a = 0.f;
                #pragma unroll
                for (int s2 = 0; s2 < 16; s2++) a += w_s[12 + s2] * mem2[s2 * 17 + lane];
                if (live) rvb[96 + lane] = c2 * a;
            }
            if (lane == 0 && live) {
                rvb[112] = c0; rvb[113] = c1; rvb[114] = c2;
            }
            __syncwarp();
        }
    }
}

// =========================== K3: out = rv_ext @ Fu^T + bc ===========================
// 128 rows/block, 256 threads. smem: Fu[64][117] + bc[64] + rvt[115][130].
#define K3_FU   0
#define K3_BC   7488
#define K3_RVT  7552
#define K3_FLOATS (K3_RVT + 115 * 130)
#define K3_BYTES  (K3_FLOATS * 4)

__global__ void __launch_bounds__(256) out_gemm(
    const float* __restrict__ bc_g,
    float* __restrict__ out_g,
    int nrows)
{
    extern __shared__ float sm[];
    float* Fu_s = sm + K3_FU;    // [64][117]
    float* bc_s = sm + K3_BC;    // [64]
    float* rvt  = sm + K3_RVT;   // [115][130] k-major, rows along 130-stride

    const int tid = threadIdx.x;
    const int row0 = blockIdx.x * 128;

    // stage Fu + bc
    for (int idx = tid; idx < 64 * 115; idx += 256) {
        int o = idx / 115, j = idx - o * 115;
        Fu_s[o * 117 + j] = g_Fu[idx];
    }
    for (int idx = tid; idx < 64; idx += 256) bc_s[idx] = bc_g[idx];

    // stage rv tile transposed (coalesced global read)
    for (int idx = tid; idx < 128 * 116; idx += 256) {
        int row = idx / 116, k = idx - row * 116;
        int grow = min(row0 + row, nrows - 1);
        float v = g_rv[(size_t)grow * 116 + k];
        if (k < 115) rvt[k * 130 + row] = v;
    }
    __syncthreads();

    const int cg = tid & 7;     // col group: o = cg + 8*i
    const int rg = tid >> 3;    // 32 row groups x 4 rows
    const int rbase = rg * 4;

    u64 a[8][2];
    #pragma unroll
    for (int i = 0; i < 8; i++) {
        float b = bc_s[cg + 8 * i];
        a[i][0] = pack2(b, b);
        a[i][1] = pack2(b, b);
    }

    #pragma unroll 5
    for (int k = 0; k < 115; k++) {
        u64 ra = *(const u64*)&rvt[k * 130 + rbase];      // rows (0,1)
        u64 rb = *(const u64*)&rvt[k * 130 + rbase + 2];  // rows (2,3)
        #pragma unroll
        for (int i = 0; i < 8; i++) {
            float w = Fu_s[(cg + 8 * i) * 117 + k];
            u64 ww = pack2(w, w);
            a[i][0] = fma2(ww, ra, a[i][0]);
            a[i][1] = fma2(ww, rb, a[i][1]);
        }
    }

    #pragma unroll
    for (int i = 0; i < 8; i++) {
        int o = cg + 8 * i;
        float v0, v1, v2, v3;
        unpack2(a[i][0], v0, v1);
        unpack2(a[i][1], v2, v3);
        int gr = row0 + rbase;
        if (gr < nrows)     out_g[(size_t)gr * 64 + o]       = v0;
        if (gr + 1 < nrows) out_g[(size_t)(gr + 1) * 64 + o] = v1;
        if (gr + 2 < nrows) out_g[(size_t)(gr + 2) * 64 + o] = v2;
        if (gr + 3 < nrows) out_g[(size_t)(gr + 3) * 64 + o] = v3;
    }
}

extern "C" void kernel_launch(void* const* d_in, const int* in_sizes, int n_in,
                              void* d_out, int out_size) {
    // metadata order (per-tier interleaved):
    // 0:q 1:mem0 2:mem1 3:mem2 4:Wp0 5:bp0 6:Wu0 7:bu0 8:Wp1 9:bp1 10:Wu1 11:bu1
    // 12:Wp2 13:bp2 14:Wu2 15:bu2 16:Wc 17:bc
    const float* q   = (const float*)d_in[0];
    const float* m0  = (const float*)d_in[1];
    const float* m1  = (const float*)d_in[2];
    const float* m2  = (const float*)d_in[3];
    const float* Wp0 = (const float*)d_in[4];
    const float* bp0 = (const float*)d_in[5];
    const float* Wu0 = (const float*)d_in[6];
    const float* bu0 = (const float*)d_in[7];
    const float* Wp1 = (const float*)d_in[8];
    const float* bp1 = (const float*)d_in[9];
    const float* Wu1 = (const float*)d_in[10];
    const float* bu1 = (const float*)d_in[11];
    const float* Wp2 = (const float*)d_in[12];
    const float* bp2 = (const float*)d_in[13];
    const float* Wu2 = (const float*)d_in[14];
    const float* bu2 = (const float*)d_in[15];
    const float* Wc  = (const float*)d_in[16];
    const float* bc  = (const float*)d_in[17];
    float* out = (float*)d_out;

    int nrows = in_sizes[0] / 64;

    cudaFuncSetAttribute(retrieval_main,
                         cudaFuncAttributeMaxDynamicSharedMemorySize, SMEM_BYTES);
    cudaFuncSetAttribute(out_gemm,
                         cudaFuncAttributeMaxDynamicSharedMemorySize, K3_BYTES);

    precompute_fu<<<64, 128>>>(Wc, Wu0, Wu1, Wu2, bu0, bu1, bu2);

    retrieval_main<<<NB, NTHR, SMEM_BYTES>>>(
        q, m0, m1, m2,
        Wp0, bp0, Wp1, bp1, Wp2, bp2, nrows);

    out_gemm<<<(nrows + 127) / 128, 256, K3_BYTES>>>(bc, out, nrows);
}

// round 15
// speedup vs baseline: 1.1148x; 1.1148x over previous
#include <cuda_runtime.h>
#include <cstdint>
#include <cstddef>

// ---------------------------------------------------------------------------
// SimultaneousRetrievalModel on GB300 (sm_103a)
// R15: revert to R13 single fused kernel; amortize weight LDS by processing
// 8 rows/warp (step A: Wp read once per 8 rows; step F': Fu read once per 8).
// 15 warps/CTA, 219 KB smem. Fu = Wc@[Wu_cat|bu] precomputed. f32x2 FMA.
// ---------------------------------------------------------------------------

#define WARPS 15
#define NTHR  (WARPS * 32)
#define NB    152

typedef unsigned long long u64;

__device__ __forceinline__ u64 pack2(float lo, float hi) {
    u64 r; asm("mov.b64 %0, {%1, %2};" : "=l"(r) : "f"(lo), "f"(hi)); return r;
}
__device__ __forceinline__ void unpack2(u64 v, float& lo, float& hi) {
    asm("mov.b64 {%0, %1}, %2;" : "=f"(lo), "=f"(hi) : "l"(v));
}
__device__ __forceinline__ u64 fma2(u64 a, u64 b, u64 c) {
    u64 d; asm("fma.rn.f32x2 %0, %1, %2, %3;" : "=l"(d) : "l"(a), "l"(b), "l"(c)); return d;
}

// Fused up-proj+classifier weights: [64][115] compact
__device__ float g_Fu[64 * 115];

__global__ void precompute_fu(const float* __restrict__ Wc,
                              const float* __restrict__ Wu0,
                              const float* __restrict__ Wu1,
                              const float* __restrict__ Wu2,
                              const float* __restrict__ bu0,
                              const float* __restrict__ bu1,
                              const float* __restrict__ bu2) {
    __shared__ float wc_row[64];
    int o = blockIdx.x;       // 64 blocks
    int j = threadIdx.x;      // 128 threads
    if (j < 64) wc_row[j] = Wc[o * 64 + j];
    __syncthreads();
    if (j < 115) {
        float s = 0.f;
        if (j < 64) {
            for (int h = 0; h < 64; h++) s += wc_row[h] * Wu0[h * 64 + j];
        } else if (j < 96) {
            int jj = j - 64;
            for (int h = 0; h < 64; h++) s += wc_row[h] * Wu1[h * 32 + jj];
        } else if (j < 112) {
            int jj = j - 96;
            for (int h = 0; h < 64; h++) s += wc_row[h] * Wu2[h * 16 + jj];
        } else {
            const float* bu = (j == 112) ? bu0 : (j == 113) ? bu1 : bu2;
            for (int h = 0; h < 64; h++) s += wc_row[h] * bu[h];
        }
        g_Fu[o * 115 + j] = s;
    }
}

// ---- block-shared weights (float offsets) ----
#define OFF_WP   0        // [112][65] rows pre-scaled by 1/sqrt(dim)
#define OFF_BP   7280     // [112] pre-scaled
#define OFF_FU   7392     // [64][117]
#define OFF_BC   14880    // [64]
#define OFF_WARP 14944

// ---- per-warp scratch (float offsets within warp region) ----
// S_RVQT: union of qt [64][10]=640 (step A only) and rvp [4][116][2]=928
#define S_RVQT 0
#define S_QP   928      // [8][112] = 896
#define S_M0   1824     // [4][65]  = 260 (pad 264)
#define S_M1   2088     // [8][33]  = 264
#define S_M2   2352     // [16][17] = 272
#define S_W    2624     // [28] (pad 32)
#define W_STRIDE 2656

#define SMEM_FLOATS (OFF_WARP + WARPS * W_STRIDE)
#define SMEM_BYTES  (SMEM_FLOATS * 4)

__global__ void __launch_bounds__(NTHR, 1) retrieval_kernel(
    const float* __restrict__ q_g,
    const float* __restrict__ m0_g,
    const float* __restrict__ m1_g,
    const float* __restrict__ m2_g,
    const float* __restrict__ Wp0, const float* __restrict__ bp0,
    const float* __restrict__ Wp1, const float* __restrict__ bp1,
    const float* __restrict__ Wp2, const float* __restrict__ bp2,
    const float* __restrict__ bc_g,
    float* __restrict__ out_g,
    int nrows)
{
    extern __shared__ float sm[];
    const int tid  = threadIdx.x;
    const int wid  = tid >> 5;
    const int lane = tid & 31;

    // ---------------- stage weights (once per block) ----------------
    {
        const float s0 = 0.125f;                  // 1/sqrt(64)
        const float s1 = 0.17677669529663687f;    // 1/sqrt(32)
        const float s2 = 0.25f;                   // 1/sqrt(16)
        for (int idx = tid; idx < 112 * 64; idx += NTHR) {
            int j = idx >> 6, h = idx & 63;
            float v;
            if (j < 64)      v = Wp0[j * 64 + h] * s0;
            else if (j < 96) v = Wp1[(j - 64) * 64 + h] * s1;
            else             v = Wp2[(j - 96) * 64 + h] * s2;
            sm[OFF_WP + j * 65 + h] = v;
        }
        for (int j = tid; j < 112; j += NTHR) {
            float v;
            if (j < 64)      v = bp0[j] * s0;
            else if (j < 96) v = bp1[j - 64] * s1;
            else             v = bp2[j - 96] * s2;
            sm[OFF_BP + j] = v;
        }
        for (int idx = tid; idx < 64 * 115; idx += NTHR) {
            int o = idx / 115, j = idx - o * 115;
            sm[OFF_FU + o * 117 + j] = g_Fu[idx];
        }
        for (int idx = tid; idx < 64; idx += NTHR) sm[OFF_BC + idx] = bc_g[idx];
    }
    __syncthreads();

    float* wbase = sm + OFF_WARP + wid * W_STRIDE;
    float* qt    = wbase + S_RVQT;   // [64][10], step A only
    float* rvp   = wbase + S_RVQT;   // [4][116][2], steps B-F (aliases qt)
    float* qp_s  = wbase + S_QP;     // [8][112]
    float* mem0  = wbase + S_M0;
    float* mem1  = wbase + S_M1;
    float* mem2  = wbase + S_M2;
    float* w_s   = wbase + S_W;

    const float* Wp_s = sm + OFF_WP;
    const float* bp_s = sm + OFF_BP;
    const float* Fu_s = sm + OFF_FU;
    const float* bc_s = sm + OFF_BC;

    const int gw = blockIdx.x * WARPS + wid;
    const int ngroups = (nrows + 7) >> 3;
    const int gstride = gridDim.x * WARPS;

    for (int g = gw; g < ngroups; g += gstride) {
        const int r0 = g * 8;

        // ---- load q for 8 rows, transposed: qt[h*10 + r] ----
        #pragma unroll
        for (int r = 0; r < 8; r++) {
            int row = min(r0 + r, nrows - 1);
            qt[lane * 10 + r]        = q_g[(size_t)row * 64 + lane];
            qt[(lane + 32) * 10 + r] = q_g[(size_t)row * 64 + lane + 32];
        }
        __syncwarp();

        // ---- step A: down-proj for 8 rows (4 pairs), Wp read once ----
        {
            int j3 = (lane < 16) ? (lane + 96) : (lane + 64);  // dup lanes>=16
            int js[4] = { lane, lane + 32, lane + 64, j3 };
            u64 ac[4][4];   // [j-slot][row-pair]
            #pragma unroll
            for (int k = 0; k < 4; k++) {
                float b = bp_s[js[k]];
                u64 bb = pack2(b, b);
                ac[k][0] = bb; ac[k][1] = bb; ac[k][2] = bb; ac[k][3] = bb;
            }
            #pragma unroll 2
            for (int h = 0; h < 64; h++) {
                u64 qa = *(const u64*)&qt[h * 10];
                u64 qb = *(const u64*)&qt[h * 10 + 2];
                u64 qc = *(const u64*)&qt[h * 10 + 4];
                u64 qd = *(const u64*)&qt[h * 10 + 6];
                #pragma unroll
                for (int k = 0; k < 4; k++) {
                    float w = Wp_s[js[k] * 65 + h];
                    u64 ww = pack2(w, w);
                    ac[k][0] = fma2(ww, qa, ac[k][0]);
                    ac[k][1] = fma2(ww, qb, ac[k][1]);
                    ac[k][2] = fma2(ww, qc, ac[k][2]);
                    ac[k][3] = fma2(ww, qd, ac[k][3]);
                }
            }
            #pragma unroll
            for (int k = 0; k < 4; k++) {
                if (k == 3 && lane >= 16) break;
                #pragma unroll
                for (int p = 0; p < 4; p++) {
                    float v0, v1;
                    unpack2(ac[k][p], v0, v1);
                    qp_s[(2 * p) * 112 + js[k]]     = v0;
                    qp_s[(2 * p + 1) * 112 + js[k]] = v1;
                }
            }
        }
        __syncwarp();   // qt dead; rvp may now overwrite

        // ---- steps B-E per row: register-resident sims + retrieved ----
        for (int r = 0; r < 8; r++) {
            int row = min(r0 + r, nrows - 1);

            // lane l owns global floats [8l, 8l+8) of each tile
            const float4* f0 = (const float4*)(m0_g + (size_t)row * 256);
            const float4* f1 = (const float4*)(m1_g + (size_t)row * 256);
            const float4* f2 = (const float4*)(m2_g + (size_t)row * 256);
            float ch0[8], ch1[8], ch2[8];
            *(float4*)&ch0[0] = f0[2 * lane];
            *(float4*)&ch0[4] = f0[2 * lane + 1];
            *(float4*)&ch1[0] = f1[2 * lane];
            *(float4*)&ch1[4] = f1[2 * lane + 1];
            *(float4*)&ch2[0] = f2[2 * lane];
            *(float4*)&ch2[4] = f2[2 * lane + 1];

            const float* qpr = qp_s + r * 112;
            float conf0, conf1, conf2;

            // tier0: 4 slots x dim64; lane = (s<<3)|hg
            {
                int hg = lane & 7;
                float qph[8];
                *(float4*)&qph[0] = *(const float4*)&qpr[hg * 8];
                *(float4*)&qph[4] = *(const float4*)&qpr[hg * 8 + 4];
                float acc = 0.f;
                #pragma unroll
                for (int k = 0; k < 8; k++) acc += ch0[k] * qph[k];
                acc += __shfl_xor_sync(0xffffffffu, acc, 1);
                acc += __shfl_xor_sync(0xffffffffu, acc, 2);
                acc += __shfl_xor_sync(0xffffffffu, acc, 4);
                float mx = acc;
                mx = fmaxf(mx, __shfl_xor_sync(0xffffffffu, mx, 8));
                mx = fmaxf(mx, __shfl_xor_sync(0xffffffffu, mx, 16));
                float e = __expf(acc - mx);
                float se = e;
                se += __shfl_xor_sync(0xffffffffu, se, 8);
                se += __shfl_xor_sync(0xffffffffu, se, 16);
                float inv = 1.f / se;
                if ((lane & 7) == 0) w_s[lane >> 3] = e * inv;
                conf0 = inv;
            }
            // tier1: 8 slots x dim32; lane = (s<<2)|hg
            {
                int hg = lane & 3;
                float qph[8];
                *(float4*)&qph[0] = *(const float4*)&qpr[64 + hg * 8];
                *(float4*)&qph[4] = *(const float4*)&qpr[64 + hg * 8 + 4];
                float acc = 0.f;
                #pragma unroll
                for (int k = 0; k < 8; k++) acc += ch1[k] * qph[k];
                acc += __shfl_xor_sync(0xffffffffu, acc, 1);
                acc += __shfl_xor_sync(0xffffffffu, acc, 2);
                float mx = acc;
                mx = fmaxf(mx, __shfl_xor_sync(0xffffffffu, mx, 4));
                mx = fmaxf(mx, __shfl_xor_sync(0xffffffffu, mx, 8));
                mx = fmaxf(mx, __shfl_xor_sync(0xffffffffu, mx, 16));
                float e = __expf(acc - mx);
                float se = e;
                se += __shfl_xor_sync(0xffffffffu, se, 4);
                se += __shfl_xor_sync(0xffffffffu, se, 8);
                se += __shfl_xor_sync(0xffffffffu, se, 16);
                float inv = 1.f / se;
                if ((lane & 3) == 0) w_s[4 + (lane >> 2)] = e * inv;
                conf1 = inv;
            }
            // tier2: 16 slots x dim16; lane = (s<<1)|hg
            {
                int hg = lane & 1;
                float qph[8];
                *(float4*)&qph[0] = *(const float4*)&qpr[96 + hg * 8];
                *(float4*)&qph[4] = *(const float4*)&qpr[96 + hg * 8 + 4];
                float acc = 0.f;
                #pragma unroll
                for (int k = 0; k < 8; k++) acc += ch2[k] * qph[k];
                acc += __shfl_xor_sync(0xffffffffu, acc, 1);
                float mx = acc;
                mx = fmaxf(mx, __shfl_xor_sync(0xffffffffu, mx, 2));
                mx = fmaxf(mx, __shfl_xor_sync(0xffffffffu, mx, 4));
                mx = fmaxf(mx, __shfl_xor_sync(0xffffffffu, mx, 8));
                mx = fmaxf(mx, __shfl_xor_sync(0xffffffffu, mx, 16));
                float e = __expf(acc - mx);
                float se = e;
                se += __shfl_xor_sync(0xffffffffu, se, 2);
                se += __shfl_xor_sync(0xffffffffu, se, 4);
                se += __shfl_xor_sync(0xffffffffu, se, 8);
                se += __shfl_xor_sync(0xffffffffu, se, 16);
                float inv = 1.f / se;
                if ((lane & 1) == 0) w_s[12 + (lane >> 1)] = e * inv;
                conf2 = inv;
            }

            // conf softmax (all lanes, redundant)
            float mm = fmaxf(conf0, fmaxf(conf1, conf2));
            float e0 = __expf(conf0 - mm), e1 = __expf(conf1 - mm), e2 = __expf(conf2 - mm);
            float cinv = 1.f / (e0 + e1 + e2);
            float c0 = e0 * cinv, c1 = e1 * cinv, c2 = e2 * cinv;

            // stage chunks into padded smem (per-lane runs)
            {
                float* d0 = &mem0[(lane >> 3) * 65 + (lane & 7) * 8];
                float* d1 = &mem1[(lane >> 2) * 33 + (lane & 3) * 8];
                float* d2 = &mem2[(lane >> 1) * 17 + (lane & 1) * 8];
                #pragma unroll
                for (int k = 0; k < 8; k++) d0[k] = ch0[k];
                #pragma unroll
                for (int k = 0; k < 8; k++) d1[k] = ch1[k];
                #pragma unroll
                for (int k = 0; k < 8; k++) d2[k] = ch2[k];
            }
            __syncwarp();

            // retrieved (c-scaled), pair-packed into rvp; c extras at j=112..114
            int pbase = (r >> 1) * 232, sub = r & 1;
            {
                float w0 = w_s[0], w1 = w_s[1], w2 = w_s[2], w3 = w_s[3];
                #pragma unroll
                for (int jj = 0; jj < 2; jj++) {
                    int j = lane + jj * 32;
                    float a = w0 * mem0[j] + w1 * mem0[65 + j]
                            + w2 * mem0[130 + j] + w3 * mem0[195 + j];
                    rvp[pbase + j * 2 + sub] = c0 * a;
                }
            }
            {
                float a = 0.f;
                #pragma unroll
                for (int s2 = 0; s2 < 8; s2++) a += w_s[4 + s2] * mem1[s2 * 33 + lane];
                rvp[pbase + (64 + lane) * 2 + sub] = c1 * a;
            }
            if (lane < 16) {
                float a = 0.f;
                #pragma unroll
                for (int s2 = 0; s2 < 16; s2++) a += w_s[12 + s2] * mem2[s2 * 17 + lane];
                rvp[pbase + (96 + lane) * 2 + sub] = c2 * a;
            }
            if (lane == 0) {
                rvp[pbase + 224 + sub] = c0;   // j=112
                rvp[pbase + 226 + sub] = c1;   // j=113
                rvp[pbase + 228 + sub] = c2;   // j=114
            }
            __syncwarp();
        }

        // ---- step F': fused up-proj+classifier for 8 rows, Fu read once ----
        {
            const int o0 = lane, o1 = lane + 32;
            float bc0 = bc_s[o0], bc1 = bc_s[o1];
            u64 a0[4], a1[4];
            #pragma unroll
            for (int p = 0; p < 4; p++) {
                a0[p] = pack2(bc0, bc0);
                a1[p] = pack2(bc1, bc1);
            }
            const float* f0r = &Fu_s[o0 * 117];
            const float* f1r = &Fu_s[o1 * 117];
            #pragma unroll 5
            for (int j = 0; j < 115; j++) {
                u64 rv0 = *(const u64*)&rvp[j * 2];
                u64 rv1 = *(const u64*)&rvp[232 + j * 2];
                u64 rv2 = *(const u64*)&rvp[464 + j * 2];
                u64 rv3 = *(const u64*)&rvp[696 + j * 2];
                float w0 = f0r[j], w1 = f1r[j];
                u64 ww0 = pack2(w0, w0), ww1 = pack2(w1, w1);
                a0[0] = fma2(ww0, rv0, a0[0]);
                a0[1] = fma2(ww0, rv1, a0[1]);
                a0[2] = fma2(ww0, rv2, a0[2]);
                a0[3] = fma2(ww0, rv3, a0[3]);
                a1[0] = fma2(ww1, rv0, a1[0]);
                a1[1] = fma2(ww1, rv1, a1[1]);
                a1[2] = fma2(ww1, rv2, a1[2]);
                a1[3] = fma2(ww1, rv3, a1[3]);
            }
            #pragma unroll
            for (int p = 0; p < 4; p++) {
                float va0, vb0, va1, vb1;
                unpack2(a0[p], va0, vb0);
                unpack2(a1[p], va1, vb1);
                int ra = r0 + 2 * p, rb = ra + 1;
                if (ra < nrows) {
                    out_g[(size_t)ra * 64 + o0] = va0;
                    out_g[(size_t)ra * 64 + o1] = va1;
                }
                if (rb < nrows) {
                    out_g[(size_t)rb * 64 + o0] = vb0;
                    out_g[(size_t)rb * 64 + o1] = vb1;
                }
            }
        }
        __syncwarp();
    }
}

extern "C" void kernel_launch(void* const* d_in, const int* in_sizes, int n_in,
                              void* d_out, int out_size) {
    // metadata order (per-tier interleaved):
    // 0:q 1:mem0 2:mem1 3:mem2 4:Wp0 5:bp0 6:Wu0 7:bu0 8:Wp1 9:bp1 10:Wu1 11:bu1
    // 12:Wp2 13:bp2 14:Wu2 15:bu2 16:Wc 17:bc
    const float* q   = (const float*)d_in[0];
    const float* m0  = (const float*)d_in[1];
    const float* m1  = (const float*)d_in[2];
    const float* m2  = (const float*)d_in[3];
    const float* Wp0 = (const float*)d_in[4];
    const float* bp0 = (const float*)d_in[5];
    const float* Wu0 = (const float*)d_in[6];
    const float* bu0 = (const float*)d_in[7];
    const float* Wp1 = (const float*)d_in[8];
    const float* bp1 = (const float*)d_in[9];
    const float* Wu1 = (const float*)d_in[10];
    const float* bu1 = (const float*)d_in[11];
    const float* Wp2 = (const float*)d_in[12];
    const float* bp2 = (const float*)d_in[13];
    const float* Wu2 = (const float*)d_in[14];
    const float* bu2 = (const float*)d_in[15];
    const float* Wc  = (const float*)d_in[16];
    const float* bc  = (const float*)d_in[17];
    float* out = (float*)d_out;

    int nrows = in_sizes[0] / 64;

    cudaFuncSetAttribute(retrieval_kernel,
                         cudaFuncAttributeMaxDynamicSharedMemorySize, SMEM_BYTES);

    precompute_fu<<<64, 128>>>(Wc, Wu0, Wu1, Wu2, bu0, bu1, bu2);

    retrieval_kernel<<<NB, NTHR, SMEM_BYTES>>>(
        q, m0, m1, m2,
        Wp0, bp0, Wp1, bp1, Wp2, bp2,
        bc, out, nrows);
}